// round 13
// baseline (speedup 1.0000x reference)
#include <cuda_runtime.h>
#include <cuda_fp16.h>
#include <cstdint>

#define BATCHN 8
#define TT 2048
#define EE 1024
#define DD 128
#define MTOT (BATCHN*TT)

// Q,K,V scratch in fp16 (4 MB each) — __device__ globals per allocation rules.
__device__ __align__(16) __half g_q[MTOT*DD];
__device__ __align__(16) __half g_k[MTOT*DD];
__device__ __align__(16) __half g_v[MTOT*DD];

__device__ __forceinline__ uint32_t smem_u32(const void* p) {
  uint32_t a;
  asm("{ .reg .u64 t; cvta.to.shared.u64 t, %1; cvt.u32.u64 %0, t; }"
      : "=r"(a) : "l"(p));
  return a;
}
__device__ __forceinline__ void ldsm_x4(uint32_t* r, uint32_t addr) {
  asm volatile(
      "ldmatrix.sync.aligned.m8n8.x4.shared.b16 {%0,%1,%2,%3}, [%4];"
      : "=r"(r[0]), "=r"(r[1]), "=r"(r[2]), "=r"(r[3]) : "r"(addr));
}
__device__ __forceinline__ void ldsm_x4_t(uint32_t* r, uint32_t addr) {
  asm volatile(
      "ldmatrix.sync.aligned.m8n8.x4.trans.shared.b16 {%0,%1,%2,%3}, [%4];"
      : "=r"(r[0]), "=r"(r[1]), "=r"(r[2]), "=r"(r[3]) : "r"(addr));
}
__device__ __forceinline__ void mma_f16(float* c, const uint32_t* a,
                                        const uint32_t* b) {
  asm volatile(
      "mma.sync.aligned.m16n8k16.row.col.f32.f16.f16.f32 "
      "{%0,%1,%2,%3}, {%4,%5,%6,%7}, {%8,%9}, {%0,%1,%2,%3};"
      : "+f"(c[0]), "+f"(c[1]), "+f"(c[2]), "+f"(c[3])
      : "r"(a[0]), "r"(a[1]), "r"(a[2]), "r"(a[3]), "r"(b[0]), "r"(b[1]));
}
__device__ __forceinline__ void bar_sync(int id, int cnt) {
  asm volatile("bar.sync %0, %1;" :: "r"(id), "r"(cnt) : "memory");
}

// ---------------------------------------------------------------------------
// QKV projection via fp16 HMMA — v2: KC=16, low-register (<=124) so TWO CTAs
// co-reside per SM (4 warps/SMSP hides HMMA/LDSM latency; 384-CTA wave tail
// shrinks).  Smem stride 24 halfs (48B): LDSM granules 3r mod 8 bijective ->
// conflict-free.  Outputs fp16; Q pre-scaled by 1/sqrt(d).
// ---------------------------------------------------------------------------
#define KC 16
#define HSTR 24
#define TILE_H (128 * HSTR)

__global__ __launch_bounds__(256, 2) void qkv_hmma_kernel(
    const float* __restrict__ X, const float* __restrict__ Wq,
    const float* __restrict__ Wk, const float* __restrict__ Wv) {
  __shared__ __half Xs[2][TILE_H];
  __shared__ __half Ws[2][TILE_H];

  const int which = blockIdx.y;
  const float* __restrict__ W = (which == 0) ? Wq : (which == 1) ? Wk : Wv;
  __half* __restrict__ outp = (which == 0) ? g_q : (which == 1) ? g_k : g_v;
  const float osc = (which == 0) ? 0.08838834764831845f : 1.0f;

  const int m0 = blockIdx.x * 128;
  const int tid = threadIdx.x;
  const int warp = tid >> 5;
  const int lane = tid & 31;
  const int wm = (warp >> 1) * 32;
  const int wn = (warp & 1) * 64;

  const int ldrow = tid >> 1;        // 0..127
  const int ldk = (tid & 1) * 8;     // 0 or 8

  const int a_row = (lane & 7) + 8 * ((lane >> 3) & 1);
  const int a_col = (lane >> 4) * 8;
  const int b_row = (lane & 7) + 8 * (lane >> 4);
  const int b_col = ((lane >> 3) & 1) * 8;

  const uint32_t xs_base = smem_u32(&Xs[0][0]);
  const uint32_t ws_base = smem_u32(&Ws[0][0]);

  float acc[2][8][4];
#pragma unroll
  for (int mt = 0; mt < 2; mt++)
#pragma unroll
    for (int nt = 0; nt < 8; nt++)
#pragma unroll
      for (int i = 0; i < 4; i++) acc[mt][nt][i] = 0.f;

  // ---- stage chunk 0 ----
  {
    float4 x0 = *(const float4*)&X[(size_t)(m0 + ldrow) * EE + ldk];
    float4 x1 = *(const float4*)&X[(size_t)(m0 + ldrow) * EE + ldk + 4];
    float wv[8];
#pragma unroll
    for (int j = 0; j < 8; j++) wv[j] = W[(size_t)(ldk + j) * DD + ldrow];
    __half2 hx[4], hw[4];
    hx[0] = __floats2half2_rn(x0.x, x0.y);
    hx[1] = __floats2half2_rn(x0.z, x0.w);
    hx[2] = __floats2half2_rn(x1.x, x1.y);
    hx[3] = __floats2half2_rn(x1.z, x1.w);
#pragma unroll
    for (int j = 0; j < 4; j++) hw[j] = __floats2half2_rn(wv[2 * j], wv[2 * j + 1]);
    *(uint4*)&Xs[0][ldrow * HSTR + ldk] = *(uint4*)&hx[0];
    *(uint4*)&Ws[0][ldrow * HSTR + ldk] = *(uint4*)&hw[0];
  }
  __syncthreads();

  for (int c = 0; c < EE / KC; c++) {
    const int cur = c & 1;
    float4 x0, x1;
    float wv[8];
    const bool more = (c + 1 < EE / KC);
    if (more) {
      const int kc = (c + 1) * KC;
      x0 = *(const float4*)&X[(size_t)(m0 + ldrow) * EE + kc + ldk];
      x1 = *(const float4*)&X[(size_t)(m0 + ldrow) * EE + kc + ldk + 4];
#pragma unroll
      for (int j = 0; j < 8; j++)
        wv[j] = W[(size_t)(kc + ldk + j) * DD + ldrow];
    }

    // ---- compute chunk c: one k16 step ----
    const uint32_t xb = xs_base + (uint32_t)(cur * TILE_H * 2);
    const uint32_t wb = ws_base + (uint32_t)(cur * TILE_H * 2);
    {
      uint32_t a[2][4];
#pragma unroll
      for (int mt = 0; mt < 2; mt++) {
        const int row = wm + mt * 16 + a_row;
        ldsm_x4(a[mt], xb + (uint32_t)((row * HSTR + a_col) * 2));
      }
      uint32_t bf[8][2];
#pragma unroll
      for (int g = 0; g < 4; g++) {
        uint32_t r[4];
        const int row = wn + g * 16 + b_row;
        ldsm_x4(r, wb + (uint32_t)((row * HSTR + b_col) * 2));
        bf[2 * g][0] = r[0]; bf[2 * g][1] = r[1];
        bf[2 * g + 1][0] = r[2]; bf[2 * g + 1][1] = r[3];
      }
#pragma unroll
      for (int mt = 0; mt < 2; mt++)
#pragma unroll
        for (int nt = 0; nt < 8; nt++) mma_f16(acc[mt][nt], a[mt], bf[nt]);
    }

    if (more) {
      const int nxt = cur ^ 1;
      __half2 hx[4], hw[4];
      hx[0] = __floats2half2_rn(x0.x, x0.y);
      hx[1] = __floats2half2_rn(x0.z, x0.w);
      hx[2] = __floats2half2_rn(x1.x, x1.y);
      hx[3] = __floats2half2_rn(x1.z, x1.w);
#pragma unroll
      for (int j = 0; j < 4; j++)
        hw[j] = __floats2half2_rn(wv[2 * j], wv[2 * j + 1]);
      *(uint4*)&Xs[nxt][ldrow * HSTR + ldk] = *(uint4*)&hx[0];
      *(uint4*)&Ws[nxt][ldrow * HSTR + ldk] = *(uint4*)&hw[0];
    }
    __syncthreads();
  }

  const int fr = lane >> 2;
  const int fc = (lane & 3) * 2;
#pragma unroll
  for (int mt = 0; mt < 2; mt++) {
    const size_t row0 = (size_t)(m0 + wm + mt * 16 + fr);
#pragma unroll
    for (int nt = 0; nt < 8; nt++) {
      const int col = wn + nt * 8 + fc;
      __half2 h01 = __floats2half2_rn(acc[mt][nt][0] * osc, acc[mt][nt][1] * osc);
      __half2 h23 = __floats2half2_rn(acc[mt][nt][2] * osc, acc[mt][nt][3] * osc);
      *(__half2*)&outp[row0 * DD + col] = h01;
      *(__half2*)&outp[(row0 + 8) * DD + col] = h23;
    }
  }
}

// ---------------------------------------------------------------------------
// Causal flash attention v8 (unchanged from R12 — 43.9us): fp16 HMMA,
// split-K warp groups, group-local barriers, end-of-qblk merge.
// ---------------------------------------------------------------------------
#define HST 136
#define QOFF 0
#define MLOFF (320 * HST)
#define ATT_SMEM_B (320 * HST * 2 + 1024)

__global__ __launch_bounds__(256) void attn_hmma_kernel(float* __restrict__ out) {
  extern __shared__ __half smh[];
  const int tid = threadIdx.x;
  const int w = tid >> 5;
  const int g = w >> 2;
  const int wg = w & 3;
  const int lane = tid & 31;
  const int b = blockIdx.y;

  const __half* __restrict__ qp = g_q + (size_t)b * TT * DD;
  const __half* __restrict__ kp = g_k + (size_t)b * TT * DD;
  const __half* __restrict__ vp = g_v + (size_t)b * TT * DD;

  const uint32_t smb = smem_u32(smh);
  const int fr = lane >> 2;
  const int fc = (lane & 3) * 2;
  const int lm = lane >> 3;
  const int r8 = lane & 7;

  const int qa_row = 16 * wg + r8 + 8 * (lm & 1);
  const int qa_colb = 8 * (lm >> 1);
  const int kb_rowoff = 8 * (lm >> 1) + r8;
  const int kb_coloff = 8 * (lm & 1);
  const int vb_rowoff = 8 * (lm & 1) + r8;
  const int vb_coloff = 8 * (lm >> 1);

  const int KOFFg = (64 + 128 * g) * HST;
  const int VOFFg = (128 + 128 * g) * HST;

  const int lt = tid & 127;
  const int ls_r = lt >> 4;
  const int ls_c = lt & 15;
  const int qs_r = tid >> 4;
  const int qs_c = tid & 15;

  float* mlx = (float*)(smh + MLOFF);
  float* Oex = (float*)(smh + 64 * HST);

  for (int pass = 0; pass < 2; pass++) {
    const int qblk = pass ? (31 - (int)blockIdx.x) : (int)blockIdx.x;
    const int nkt = qblk + 1;

#pragma unroll
    for (int it = 0; it < 4; it++) {
      const int r = qs_r + 16 * it;
      uint4 v = *((const uint4*)qp + (size_t)(qblk * 64 + r) * 16 + qs_c);
      *(uint4*)&smh[QOFF + r * HST + qs_c * 8] = v;
    }
    uint4 pk4[8], pv4[8];
#pragma unroll
    for (int it = 0; it < 8; it++) {
      const size_t r = (size_t)g * 64 + ls_r + 8 * it;
      pk4[it] = *((const uint4*)kp + r * 16 + ls_c);
      pv4[it] = *((const uint4*)vp + r * 16 + ls_c);
    }
    __syncthreads();

    uint32_t qa[8][4];
#pragma unroll
    for (int ks = 0; ks < 8; ks++)
      ldsm_x4(qa[ks], smb + (uint32_t)((qa_row * HST + 16 * ks + qa_colb) * 2));

    float m0 = -1e30f, m1 = -1e30f, l0 = 0.f, l1 = 0.f;
    float ov[16][4];
#pragma unroll
    for (int nt = 0; nt < 16; nt++)
#pragma unroll
      for (int i = 0; i < 4; i++) ov[nt][i] = 0.f;

    for (int kt = g; kt < nkt; kt += 2) {
      bar_sync(g + 1, 128);
#pragma unroll
      for (int it = 0; it < 8; it++) {
        const int r = ls_r + 8 * it;
        *(uint4*)&smh[KOFFg + r * HST + ls_c * 8] = pk4[it];
        *(uint4*)&smh[VOFFg + r * HST + ls_c * 8] = pv4[it];
      }
      bar_sync(g + 1, 128);

      if (kt + 2 < nkt) {
        const size_t krow = (size_t)(kt + 2) * 64;
#pragma unroll
        for (int it = 0; it < 8; it++)
          pk4[it] = *((const uint4*)kp + (krow + ls_r + 8 * it) * 16 + ls_c);
      }

      float sc_[8][4];
#pragma unroll
      for (int nt = 0; nt < 8; nt++)
#pragma unroll
        for (int i = 0; i < 4; i++) sc_[nt][i] = 0.f;

#pragma unroll
      for (int ks = 0; ks < 8; ks++) {
        uint32_t bq[4][4];
#pragma unroll
        for (int np = 0; np < 4; np++)
          ldsm_x4(bq[np], smb + (uint32_t)((KOFFg + (16 * np + kb_rowoff) * HST +
                                            16 * ks + kb_coloff) * 2));
#pragma unroll
        for (int nt = 0; nt < 8; nt++)
          mma_f16(sc_[nt], qa[ks], &bq[nt >> 1][(nt & 1) * 2]);
      }

      if (kt + 2 < nkt) {
        const size_t krow = (size_t)(kt + 2) * 64;
#pragma unroll
        for (int it = 0; it < 8; it++)
          pv4[it] = *((const uint4*)vp + (krow + ls_r + 8 * it) * 16 + ls_c);
      }

      if (kt == qblk) {
        const int q0r = qblk * 64 + 16 * wg + fr;
        const int q1r = q0r + 8;
#pragma unroll
        for (int nt = 0; nt < 8; nt++) {
          const int k0 = kt * 64 + nt * 8 + fc;
          if (k0 > q0r) sc_[nt][0] = -1e30f;
          if (k0 + 1 > q0r) sc_[nt][1] = -1e30f;
          if (k0 > q1r) sc_[nt][2] = -1e30f;
          if (k0 + 1 > q1r) sc_[nt][3] = -1e30f;
        }
      }

      float mx0 = sc_[0][0], mx1 = sc_[0][2];
#pragma unroll
      for (int nt = 0; nt < 8; nt++) {
        mx0 = fmaxf(mx0, fmaxf(sc_[nt][0], sc_[nt][1]));
        mx1 = fmaxf(mx1, fmaxf(sc_[nt][2], sc_[nt][3]));
      }
      mx0 = fmaxf(mx0, __shfl_xor_sync(0xffffffffu, mx0, 1));
      mx0 = fmaxf(mx0, __shfl_xor_sync(0xffffffffu, mx0, 2));
      mx1 = fmaxf(mx1, __shfl_xor_sync(0xffffffffu, mx1, 1));
      mx1 = fmaxf(mx1, __shfl_xor_sync(0xffffffffu, mx1, 2));
      const float mn0 = fmaxf(m0, mx0);
      const float mn1 = fmaxf(m1, mx1);
      const float al0 = __expf(m0 - mn0);
      const float al1 = __expf(m1 - mn1);
      m0 = mn0; m1 = mn1;

      uint32_t P2[8][2];
      float s0 = 0.f, s1 = 0.f;
#pragma unroll
      for (int nt = 0; nt < 8; nt++) {
        float p0 = __expf(sc_[nt][0] - mn0);
        float p1 = __expf(sc_[nt][1] - mn0);
        float p2 = __expf(sc_[nt][2] - mn1);
        float p3 = __expf(sc_[nt][3] - mn1);
        s0 += p0 + p1;
        s1 += p2 + p3;
        __half2 h01 = __floats2half2_rn(p0, p1);
        __half2 h23 = __floats2half2_rn(p2, p3);
        P2[nt][0] = *(uint32_t*)&h01;
        P2[nt][1] = *(uint32_t*)&h23;
      }
      s0 += __shfl_xor_sync(0xffffffffu, s0, 1);
      s0 += __shfl_xor_sync(0xffffffffu, s0, 2);
      s1 += __shfl_xor_sync(0xffffffffu, s1, 1);
      s1 += __shfl_xor_sync(0xffffffffu, s1, 2);
      l0 = l0 * al0 + s0;
      l1 = l1 * al1 + s1;

#pragma unroll
      for (int nt = 0; nt < 16; nt++) {
        ov[nt][0] *= al0; ov[nt][1] *= al0;
        ov[nt][2] *= al1; ov[nt][3] *= al1;
      }

#pragma unroll
      for (int kv = 0; kv < 4; kv++) {
        uint32_t av[4] = {P2[2 * kv][0], P2[2 * kv][1],
                          P2[2 * kv + 1][0], P2[2 * kv + 1][1]};
#pragma unroll
        for (int np = 0; np < 8; np++) {
          uint32_t bv[4];
          ldsm_x4_t(bv, smb + (uint32_t)((VOFFg + (16 * kv + vb_rowoff) * HST +
                                          16 * np + vb_coloff) * 2));
          mma_f16(ov[2 * np], av, &bv[0]);
          mma_f16(ov[2 * np + 1], av, &bv[2]);
        }
      }
    }

    // ================= cross-group merge =================
    const int row0 = 16 * wg + fr;
    const int row1 = row0 + 8;
    __syncthreads();
    if ((lane & 3) == 0) {
      mlx[(g * 64 + row0) * 2 + 0] = m0;
      mlx[(g * 64 + row0) * 2 + 1] = l0;
      mlx[(g * 64 + row1) * 2 + 0] = m1;
      mlx[(g * 64 + row1) * 2 + 1] = l1;
    }
    __syncthreads();
    const int og = 1 - g;
    const float mo0 = mlx[(og * 64 + row0) * 2 + 0];
    const float lo0 = mlx[(og * 64 + row0) * 2 + 1];
    const float mo1 = mlx[(og * 64 + row1) * 2 + 0];
    const float lo1 = mlx[(og * 64 + row1) * 2 + 1];
    const float mm0 = fmaxf(m0, mo0);
    const float mm1 = fmaxf(m1, mo1);
    const float sown0 = __expf(m0 - mm0);
    const float sown1 = __expf(m1 - mm1);
    const float lf0 = l0 * sown0 + lo0 * __expf(mo0 - mm0);
    const float lf1 = l1 * sown1 + lo1 * __expf(mo1 - mm1);
#pragma unroll
    for (int nt = 0; nt < 16; nt++) {
      ov[nt][0] *= sown0; ov[nt][1] *= sown0;
      ov[nt][2] *= sown1; ov[nt][3] *= sown1;
    }
    if (g == 1) {
#pragma unroll
      for (int nt = 0; nt < 16; nt++) {
        const int col = nt * 8 + fc;
        *(float2*)&Oex[row0 * 128 + col] = make_float2(ov[nt][0], ov[nt][1]);
        *(float2*)&Oex[row1 * 128 + col] = make_float2(ov[nt][2], ov[nt][3]);
      }
    }
    __syncthreads();
    if (g == 0) {
      const float i0 = 1.f / lf0;
      const float i1 = 1.f / lf1;
      const size_t gr0 = (size_t)b * TT + (size_t)qblk * 64 + row0;
#pragma unroll
      for (int nt = 0; nt < 16; nt++) {
        const int col = nt * 8 + fc;
        float2 p0 = *(const float2*)&Oex[row0 * 128 + col];
        float2 p1 = *(const float2*)&Oex[row1 * 128 + col];
        *(float2*)&out[gr0 * DD + col] =
            make_float2((ov[nt][0] + p0.x) * i0, (ov[nt][1] + p0.y) * i0);
        *(float2*)&out[(gr0 + 8) * DD + col] =
            make_float2((ov[nt][2] + p1.x) * i1, (ov[nt][3] + p1.y) * i1);
      }
    }
  }
}

// ---------------------------------------------------------------------------
extern "C" void kernel_launch(void* const* d_in, const int* in_sizes, int n_in,
                              void* d_out, int out_size) {
  const float* X = (const float*)d_in[0];
  const float* Wq = (const float*)d_in[1];
  const float* Wk = (const float*)d_in[2];
  const float* Wv = (const float*)d_in[3];
  float* out = (float*)d_out;

  qkv_hmma_kernel<<<dim3(128, 3), 256>>>(X, Wq, Wk, Wv);

  cudaFuncSetAttribute((const void*)attn_hmma_kernel,
                       cudaFuncAttributeMaxDynamicSharedMemorySize, ATT_SMEM_B);
  attn_hmma_kernel<<<dim3(16, BATCHN), 256, ATT_SMEM_B>>>(out);
}

// round 14
// speedup vs baseline: 1.1369x; 1.1369x over previous
#include <cuda_runtime.h>
#include <cuda_fp16.h>
#include <cstdint>

#define BATCHN 8
#define TT 2048
#define EE 1024
#define DD 128
#define MTOT (BATCHN*TT)

// fp16 scratch — __device__ globals per allocation rules.
__device__ __align__(16) __half g_x[MTOT*EE];        // 32 MB: X in fp16
__device__ __align__(16) __half g_wt[3*DD*EE];       // 768 KB: W^T fp16 [which][n][k]
__device__ __align__(16) __half g_q[MTOT*DD];
__device__ __align__(16) __half g_k[MTOT*DD];
__device__ __align__(16) __half g_v[MTOT*DD];

__device__ __forceinline__ uint32_t smem_u32(const void* p) {
  uint32_t a;
  asm("{ .reg .u64 t; cvta.to.shared.u64 t, %1; cvt.u32.u64 %0, t; }"
      : "=r"(a) : "l"(p));
  return a;
}
__device__ __forceinline__ void ldsm_x4(uint32_t* r, uint32_t addr) {
  asm volatile(
      "ldmatrix.sync.aligned.m8n8.x4.shared.b16 {%0,%1,%2,%3}, [%4];"
      : "=r"(r[0]), "=r"(r[1]), "=r"(r[2]), "=r"(r[3]) : "r"(addr));
}
__device__ __forceinline__ void ldsm_x4_t(uint32_t* r, uint32_t addr) {
  asm volatile(
      "ldmatrix.sync.aligned.m8n8.x4.trans.shared.b16 {%0,%1,%2,%3}, [%4];"
      : "=r"(r[0]), "=r"(r[1]), "=r"(r[2]), "=r"(r[3]) : "r"(addr));
}
__device__ __forceinline__ void mma_f16(float* c, const uint32_t* a,
                                        const uint32_t* b) {
  asm volatile(
      "mma.sync.aligned.m16n8k16.row.col.f32.f16.f16.f32 "
      "{%0,%1,%2,%3}, {%4,%5,%6,%7}, {%8,%9}, {%0,%1,%2,%3};"
      : "+f"(c[0]), "+f"(c[1]), "+f"(c[2]), "+f"(c[3])
      : "r"(a[0]), "r"(a[1]), "r"(a[2]), "r"(a[3]), "r"(b[0]), "r"(b[1]));
}
__device__ __forceinline__ void bar_sync(int id, int cnt) {
  asm volatile("bar.sync %0, %1;" :: "r"(id), "r"(cnt) : "memory");
}

// ---------------------------------------------------------------------------
// Prep 1: X fp32 -> fp16 (memory-bound, ~12us).  8 floats per thread.
// ---------------------------------------------------------------------------
__global__ __launch_bounds__(256) void prep_x_kernel(const float* __restrict__ X) {
  const size_t i = ((size_t)blockIdx.x * 256 + threadIdx.x) * 8;
  float4 a = *(const float4*)&X[i];
  float4 b = *(const float4*)&X[i + 4];
  __half2 h[4];
  h[0] = __floats2half2_rn(a.x, a.y);
  h[1] = __floats2half2_rn(a.z, a.w);
  h[2] = __floats2half2_rn(b.x, b.y);
  h[3] = __floats2half2_rn(b.z, b.w);
  *(uint4*)&g_x[i] = *(uint4*)&h[0];
}

// ---------------------------------------------------------------------------
// Prep 2: W [k][n] fp32 -> Wt [which][n][k] fp16; Wq scaled by 1/sqrt(d).
// One thread per output element (writes coalesced; tiny tensor).
// ---------------------------------------------------------------------------
__global__ __launch_bounds__(256) void prep_w_kernel(
    const float* __restrict__ Wq, const float* __restrict__ Wk,
    const float* __restrict__ Wv) {
  const int which = blockIdx.y;
  const float* __restrict__ W = (which == 0) ? Wq : (which == 1) ? Wk : Wv;
  const float sc = (which == 0) ? 0.08838834764831845f : 1.0f;
  const int idx = blockIdx.x * 256 + threadIdx.x;  // n*1024 + k
  const int n = idx >> 10;
  const int k = idx & 1023;
  g_wt[(size_t)which * DD * EE + idx] = __float2half_rn(W[(size_t)k * DD + n] * sc);
}

// ---------------------------------------------------------------------------
// QKV projection via fp16 HMMA — v3: all-fp16 feed (no cvt, no scalar LDG).
// KC=32, CTA tile 128x128, 8 warps (4m x 2n), double-buffered, stride 40.
// Per chunk per thread: 4x LDG.128 + 4x STS.128 + 6 LDSM + 16 MMA.
// grid = (128, 3).
// ---------------------------------------------------------------------------
#define KC 32
#define HSTR 40
#define TILE_H (128 * HSTR)

__global__ __launch_bounds__(256) void qkv_hmma_kernel() {
  __shared__ __half Xs[2][TILE_H];
  __shared__ __half Ws[2][TILE_H];

  const int which = blockIdx.y;
  const __half* __restrict__ Wt = g_wt + (size_t)which * DD * EE;
  __half* __restrict__ outp = (which == 0) ? g_q : (which == 1) ? g_k : g_v;

  const int m0 = blockIdx.x * 128;
  const int tid = threadIdx.x;
  const int warp = tid >> 5;
  const int lane = tid & 31;
  const int wm = (warp >> 1) * 32;
  const int wn = (warp & 1) * 64;

  const int ldrow = tid >> 1;        // 0..127
  const int ldk16 = (tid & 1) * 16;  // 0 or 16 (halfs)

  const int a_row = (lane & 7) + 8 * ((lane >> 3) & 1);
  const int a_col = (lane >> 4) * 8;
  const int b_row = (lane & 7) + 8 * (lane >> 4);
  const int b_col = ((lane >> 3) & 1) * 8;

  const uint32_t xs_base = smem_u32(&Xs[0][0]);
  const uint32_t ws_base = smem_u32(&Ws[0][0]);

  const __half* xrow = g_x + (size_t)(m0 + ldrow) * EE;
  const __half* wrow = Wt + (size_t)ldrow * EE;

  float acc[2][8][4];
#pragma unroll
  for (int mt = 0; mt < 2; mt++)
#pragma unroll
    for (int nt = 0; nt < 8; nt++)
#pragma unroll
      for (int i = 0; i < 4; i++) acc[mt][nt][i] = 0.f;

  // ---- stage chunk 0 ----
  {
    uint4 x0 = *(const uint4*)&xrow[ldk16];
    uint4 x1 = *(const uint4*)&xrow[ldk16 + 8];
    uint4 w0 = *(const uint4*)&wrow[ldk16];
    uint4 w1 = *(const uint4*)&wrow[ldk16 + 8];
    *(uint4*)&Xs[0][ldrow * HSTR + ldk16] = x0;
    *(uint4*)&Xs[0][ldrow * HSTR + ldk16 + 8] = x1;
    *(uint4*)&Ws[0][ldrow * HSTR + ldk16] = w0;
    *(uint4*)&Ws[0][ldrow * HSTR + ldk16 + 8] = w1;
  }
  __syncthreads();

  for (int c = 0; c < EE / KC; c++) {
    const int cur = c & 1;
    uint4 x0, x1, w0, w1;
    const bool more = (c + 1 < EE / KC);
    if (more) {
      const int kc = (c + 1) * KC;
      x0 = *(const uint4*)&xrow[kc + ldk16];
      x1 = *(const uint4*)&xrow[kc + ldk16 + 8];
      w0 = *(const uint4*)&wrow[kc + ldk16];
      w1 = *(const uint4*)&wrow[kc + ldk16 + 8];
    }

    const uint32_t xb = xs_base + (uint32_t)(cur * TILE_H * 2);
    const uint32_t wb = ws_base + (uint32_t)(cur * TILE_H * 2);
#pragma unroll
    for (int s = 0; s < 2; s++) {
      uint32_t a[2][4];
#pragma unroll
      for (int mt = 0; mt < 2; mt++) {
        const int row = wm + mt * 16 + a_row;
        ldsm_x4(a[mt], xb + (uint32_t)((row * HSTR + a_col + s * 16) * 2));
      }
      uint32_t bf[8][2];
#pragma unroll
      for (int g = 0; g < 4; g++) {
        uint32_t r[4];
        const int row = wn + g * 16 + b_row;
        ldsm_x4(r, wb + (uint32_t)((row * HSTR + b_col + s * 16) * 2));
        bf[2 * g][0] = r[0]; bf[2 * g][1] = r[1];
        bf[2 * g + 1][0] = r[2]; bf[2 * g + 1][1] = r[3];
      }
#pragma unroll
      for (int mt = 0; mt < 2; mt++)
#pragma unroll
        for (int nt = 0; nt < 8; nt++) mma_f16(acc[mt][nt], a[mt], bf[nt]);
    }

    if (more) {
      const int nxt = cur ^ 1;
      *(uint4*)&Xs[nxt][ldrow * HSTR + ldk16] = x0;
      *(uint4*)&Xs[nxt][ldrow * HSTR + ldk16 + 8] = x1;
      *(uint4*)&Ws[nxt][ldrow * HSTR + ldk16] = w0;
      *(uint4*)&Ws[nxt][ldrow * HSTR + ldk16 + 8] = w1;
    }
    __syncthreads();
  }

  const int fr = lane >> 2;
  const int fc = (lane & 3) * 2;
#pragma unroll
  for (int mt = 0; mt < 2; mt++) {
    const size_t row0 = (size_t)(m0 + wm + mt * 16 + fr);
#pragma unroll
    for (int nt = 0; nt < 8; nt++) {
      const int col = wn + nt * 8 + fc;
      __half2 h01 = __floats2half2_rn(acc[mt][nt][0], acc[mt][nt][1]);
      __half2 h23 = __floats2half2_rn(acc[mt][nt][2], acc[mt][nt][3]);
      *(__half2*)&outp[row0 * DD + col] = h01;
      *(__half2*)&outp[(row0 + 8) * DD + col] = h23;
    }
  }
}

// ---------------------------------------------------------------------------
// Causal flash attention v8 (unchanged — 43.9us): fp16 HMMA, split-K warp
// groups, group-local barriers, end-of-qblk merge.
// ---------------------------------------------------------------------------
#define HST 136
#define QOFF 0
#define MLOFF (320 * HST)
#define ATT_SMEM_B (320 * HST * 2 + 1024)

__global__ __launch_bounds__(256) void attn_hmma_kernel(float* __restrict__ out) {
  extern __shared__ __half smh[];
  const int tid = threadIdx.x;
  const int w = tid >> 5;
  const int g = w >> 2;
  const int wg = w & 3;
  const int lane = tid & 31;
  const int b = blockIdx.y;

  const __half* __restrict__ qp = g_q + (size_t)b * TT * DD;
  const __half* __restrict__ kp = g_k + (size_t)b * TT * DD;
  const __half* __restrict__ vp = g_v + (size_t)b * TT * DD;

  const uint32_t smb = smem_u32(smh);
  const int fr = lane >> 2;
  const int fc = (lane & 3) * 2;
  const int lm = lane >> 3;
  const int r8 = lane & 7;

  const int qa_row = 16 * wg + r8 + 8 * (lm & 1);
  const int qa_colb = 8 * (lm >> 1);
  const int kb_rowoff = 8 * (lm >> 1) + r8;
  const int kb_coloff = 8 * (lm & 1);
  const int vb_rowoff = 8 * (lm & 1) + r8;
  const int vb_coloff = 8 * (lm >> 1);

  const int KOFFg = (64 + 128 * g) * HST;
  const int VOFFg = (128 + 128 * g) * HST;

  const int lt = tid & 127;
  const int ls_r = lt >> 4;
  const int ls_c = lt & 15;
  const int qs_r = tid >> 4;
  const int qs_c = tid & 15;

  float* mlx = (float*)(smh + MLOFF);
  float* Oex = (float*)(smh + 64 * HST);

  for (int pass = 0; pass < 2; pass++) {
    const int qblk = pass ? (31 - (int)blockIdx.x) : (int)blockIdx.x;
    const int nkt = qblk + 1;

#pragma unroll
    for (int it = 0; it < 4; it++) {
      const int r = qs_r + 16 * it;
      uint4 v = *((const uint4*)qp + (size_t)(qblk * 64 + r) * 16 + qs_c);
      *(uint4*)&smh[QOFF + r * HST + qs_c * 8] = v;
    }
    uint4 pk4[8], pv4[8];
#pragma unroll
    for (int it = 0; it < 8; it++) {
      const size_t r = (size_t)g * 64 + ls_r + 8 * it;
      pk4[it] = *((const uint4*)kp + r * 16 + ls_c);
      pv4[it] = *((const uint4*)vp + r * 16 + ls_c);
    }
    __syncthreads();

    uint32_t qa[8][4];
#pragma unroll
    for (int ks = 0; ks < 8; ks++)
      ldsm_x4(qa[ks], smb + (uint32_t)((qa_row * HST + 16 * ks + qa_colb) * 2));

    float m0 = -1e30f, m1 = -1e30f, l0 = 0.f, l1 = 0.f;
    float ov[16][4];
#pragma unroll
    for (int nt = 0; nt < 16; nt++)
#pragma unroll
      for (int i = 0; i < 4; i++) ov[nt][i] = 0.f;

    for (int kt = g; kt < nkt; kt += 2) {
      bar_sync(g + 1, 128);
#pragma unroll
      for (int it = 0; it < 8; it++) {
        const int r = ls_r + 8 * it;
        *(uint4*)&smh[KOFFg + r * HST + ls_c * 8] = pk4[it];
        *(uint4*)&smh[VOFFg + r * HST + ls_c * 8] = pv4[it];
      }
      bar_sync(g + 1, 128);

      if (kt + 2 < nkt) {
        const size_t krow = (size_t)(kt + 2) * 64;
#pragma unroll
        for (int it = 0; it < 8; it++)
          pk4[it] = *((const uint4*)kp + (krow + ls_r + 8 * it) * 16 + ls_c);
      }

      float sc_[8][4];
#pragma unroll
      for (int nt = 0; nt < 8; nt++)
#pragma unroll
        for (int i = 0; i < 4; i++) sc_[nt][i] = 0.f;

#pragma unroll
      for (int ks = 0; ks < 8; ks++) {
        uint32_t bq[4][4];
#pragma unroll
        for (int np = 0; np < 4; np++)
          ldsm_x4(bq[np], smb + (uint32_t)((KOFFg + (16 * np + kb_rowoff) * HST +
                                            16 * ks + kb_coloff) * 2));
#pragma unroll
        for (int nt = 0; nt < 8; nt++)
          mma_f16(sc_[nt], qa[ks], &bq[nt >> 1][(nt & 1) * 2]);
      }

      if (kt + 2 < nkt) {
        const size_t krow = (size_t)(kt + 2) * 64;
#pragma unroll
        for (int it = 0; it < 8; it++)
          pv4[it] = *((const uint4*)vp + (krow + ls_r + 8 * it) * 16 + ls_c);
      }

      if (kt == qblk) {
        const int q0r = qblk * 64 + 16 * wg + fr;
        const int q1r = q0r + 8;
#pragma unroll
        for (int nt = 0; nt < 8; nt++) {
          const int k0 = kt * 64 + nt * 8 + fc;
          if (k0 > q0r) sc_[nt][0] = -1e30f;
          if (k0 + 1 > q0r) sc_[nt][1] = -1e30f;
          if (k0 > q1r) sc_[nt][2] = -1e30f;
          if (k0 + 1 > q1r) sc_[nt][3] = -1e30f;
        }
      }

      float mx0 = sc_[0][0], mx1 = sc_[0][2];
#pragma unroll
      for (int nt = 0; nt < 8; nt++) {
        mx0 = fmaxf(mx0, fmaxf(sc_[nt][0], sc_[nt][1]));
        mx1 = fmaxf(mx1, fmaxf(sc_[nt][2], sc_[nt][3]));
      }
      mx0 = fmaxf(mx0, __shfl_xor_sync(0xffffffffu, mx0, 1));
      mx0 = fmaxf(mx0, __shfl_xor_sync(0xffffffffu, mx0, 2));
      mx1 = fmaxf(mx1, __shfl_xor_sync(0xffffffffu, mx1, 1));
      mx1 = fmaxf(mx1, __shfl_xor_sync(0xffffffffu, mx1, 2));
      const float mn0 = fmaxf(m0, mx0);
      const float mn1 = fmaxf(m1, mx1);
      const float al0 = __expf(m0 - mn0);
      const float al1 = __expf(m1 - mn1);
      m0 = mn0; m1 = mn1;

      uint32_t P2[8][2];
      float s0 = 0.f, s1 = 0.f;
#pragma unroll
      for (int nt = 0; nt < 8; nt++) {
        float p0 = __expf(sc_[nt][0] - mn0);
        float p1 = __expf(sc_[nt][1] - mn0);
        float p2 = __expf(sc_[nt][2] - mn1);
        float p3 = __expf(sc_[nt][3] - mn1);
        s0 += p0 + p1;
        s1 += p2 + p3;
        __half2 h01 = __floats2half2_rn(p0, p1);
        __half2 h23 = __floats2half2_rn(p2, p3);
        P2[nt][0] = *(uint32_t*)&h01;
        P2[nt][1] = *(uint32_t*)&h23;
      }
      s0 += __shfl_xor_sync(0xffffffffu, s0, 1);
      s0 += __shfl_xor_sync(0xffffffffu, s0, 2);
      s1 += __shfl_xor_sync(0xffffffffu, s1, 1);
      s1 += __shfl_xor_sync(0xffffffffu, s1, 2);
      l0 = l0 * al0 + s0;
      l1 = l1 * al1 + s1;

#pragma unroll
      for (int nt = 0; nt < 16; nt++) {
        ov[nt][0] *= al0; ov[nt][1] *= al0;
        ov[nt][2] *= al1; ov[nt][3] *= al1;
      }

#pragma unroll
      for (int kv = 0; kv < 4; kv++) {
        uint32_t av[4] = {P2[2 * kv][0], P2[2 * kv][1],
                          P2[2 * kv + 1][0], P2[2 * kv + 1][1]};
#pragma unroll
        for (int np = 0; np < 8; np++) {
          uint32_t bv[4];
          ldsm_x4_t(bv, smb + (uint32_t)((VOFFg + (16 * kv + vb_rowoff) * HST +
                                          16 * np + vb_coloff) * 2));
          mma_f16(ov[2 * np], av, &bv[0]);
          mma_f16(ov[2 * np + 1], av, &bv[2]);
        }
      }
    }

    // ================= cross-group merge =================
    const int row0 = 16 * wg + fr;
    const int row1 = row0 + 8;
    __syncthreads();
    if ((lane & 3) == 0) {
      mlx[(g * 64 + row0) * 2 + 0] = m0;
      mlx[(g * 64 + row0) * 2 + 1] = l0;
      mlx[(g * 64 + row1) * 2 + 0] = m1;
      mlx[(g * 64 + row1) * 2 + 1] = l1;
    }
    __syncthreads();
    const int og = 1 - g;
    const float mo0 = mlx[(og * 64 + row0) * 2 + 0];
    const float lo0 = mlx[(og * 64 + row0) * 2 + 1];
    const float mo1 = mlx[(og * 64 + row1) * 2 + 0];
    const float lo1 = mlx[(og * 64 + row1) * 2 + 1];
    const float mm0 = fmaxf(m0, mo0);
    const float mm1 = fmaxf(m1, mo1);
    const float sown0 = __expf(m0 - mm0);
    const float sown1 = __expf(m1 - mm1);
    const float lf0 = l0 * sown0 + lo0 * __expf(mo0 - mm0);
    const float lf1 = l1 * sown1 + lo1 * __expf(mo1 - mm1);
#pragma unroll
    for (int nt = 0; nt < 16; nt++) {
      ov[nt][0] *= sown0; ov[nt][1] *= sown0;
      ov[nt][2] *= sown1; ov[nt][3] *= sown1;
    }
    if (g == 1) {
#pragma unroll
      for (int nt = 0; nt < 16; nt++) {
        const int col = nt * 8 + fc;
        *(float2*)&Oex[row0 * 128 + col] = make_float2(ov[nt][0], ov[nt][1]);
        *(float2*)&Oex[row1 * 128 + col] = make_float2(ov[nt][2], ov[nt][3]);
      }
    }
    __syncthreads();
    if (g == 0) {
      const float i0 = 1.f / lf0;
      const float i1 = 1.f / lf1;
      const size_t gr0 = (size_t)b * TT + (size_t)qblk * 64 + row0;
#pragma unroll
      for (int nt = 0; nt < 16; nt++) {
        const int col = nt * 8 + fc;
        float2 p0 = *(const float2*)&Oex[row0 * 128 + col];
        float2 p1 = *(const float2*)&Oex[row1 * 128 + col];
        *(float2*)&out[gr0 * DD + col] =
            make_float2((ov[nt][0] + p0.x) * i0, (ov[nt][1] + p0.y) * i0);
        *(float2*)&out[(gr0 + 8) * DD + col] =
            make_float2((ov[nt][2] + p1.x) * i1, (ov[nt][3] + p1.y) * i1);
      }
    }
  }
}

// ---------------------------------------------------------------------------
extern "C" void kernel_launch(void* const* d_in, const int* in_sizes, int n_in,
                              void* d_out, int out_size) {
  const float* X = (const float*)d_in[0];
  const float* Wq = (const float*)d_in[1];
  const float* Wk = (const float*)d_in[2];
  const float* Wv = (const float*)d_in[3];
  float* out = (float*)d_out;

  prep_x_kernel<<<(MTOT * EE) / (256 * 8), 256>>>(X);
  prep_w_kernel<<<dim3((DD * EE) / 256, 3), 256>>>(Wq, Wk, Wv);
  qkv_hmma_kernel<<<dim3(128, 3), 256>>>();

  cudaFuncSetAttribute((const void*)attn_hmma_kernel,
                       cudaFuncAttributeMaxDynamicSharedMemorySize, ATT_SMEM_B);
  attn_hmma_kernel<<<dim3(16, BATCHN), 256, ATT_SMEM_B>>>(out);
}

// round 15
// speedup vs baseline: 1.1549x; 1.0158x over previous
#include <cuda_runtime.h>
#include <cuda_fp16.h>
#include <cstdint>

#define BATCHN 8
#define TT 2048
#define EE 1024
#define DD 128
#define MTOT (BATCHN*TT)

// fp16 scratch — __device__ globals per allocation rules.
__device__ __align__(16) __half g_x[MTOT*EE];        // 32 MB: X in fp16
__device__ __align__(16) __half g_wt[3*DD*EE];       // 768 KB: W^T fp16 [which][n][k]
__device__ __align__(16) __half g_q[MTOT*DD];
__device__ __align__(16) __half g_k[MTOT*DD];
__device__ __align__(16) __half g_v[MTOT*DD];

__device__ __forceinline__ uint32_t smem_u32(const void* p) {
  uint32_t a;
  asm("{ .reg .u64 t; cvta.to.shared.u64 t, %1; cvt.u32.u64 %0, t; }"
      : "=r"(a) : "l"(p));
  return a;
}
__device__ __forceinline__ void ldsm_x4(uint32_t* r, uint32_t addr) {
  asm volatile(
      "ldmatrix.sync.aligned.m8n8.x4.shared.b16 {%0,%1,%2,%3}, [%4];"
      : "=r"(r[0]), "=r"(r[1]), "=r"(r[2]), "=r"(r[3]) : "r"(addr));
}
__device__ __forceinline__ void ldsm_x4_t(uint32_t* r, uint32_t addr) {
  asm volatile(
      "ldmatrix.sync.aligned.m8n8.x4.trans.shared.b16 {%0,%1,%2,%3}, [%4];"
      : "=r"(r[0]), "=r"(r[1]), "=r"(r[2]), "=r"(r[3]) : "r"(addr));
}
__device__ __forceinline__ void mma_f16(float* c, const uint32_t* a,
                                        const uint32_t* b) {
  asm volatile(
      "mma.sync.aligned.m16n8k16.row.col.f32.f16.f16.f32 "
      "{%0,%1,%2,%3}, {%4,%5,%6,%7}, {%8,%9}, {%0,%1,%2,%3};"
      : "+f"(c[0]), "+f"(c[1]), "+f"(c[2]), "+f"(c[3])
      : "r"(a[0]), "r"(a[1]), "r"(a[2]), "r"(a[3]), "r"(b[0]), "r"(b[1]));
}
__device__ __forceinline__ void bar_sync(int id, int cnt) {
  asm volatile("bar.sync %0, %1;" :: "r"(id), "r"(cnt) : "memory");
}

// ---------------------------------------------------------------------------
// Prep 1: X fp32 -> fp16 (memory-bound).  8 floats per thread.
// ---------------------------------------------------------------------------
__global__ __launch_bounds__(256) void prep_x_kernel(const float* __restrict__ X) {
  const size_t i = ((size_t)blockIdx.x * 256 + threadIdx.x) * 8;
  float4 a = *(const float4*)&X[i];
  float4 b = *(const float4*)&X[i + 4];
  __half2 h[4];
  h[0] = __floats2half2_rn(a.x, a.y);
  h[1] = __floats2half2_rn(a.z, a.w);
  h[2] = __floats2half2_rn(b.x, b.y);
  h[3] = __floats2half2_rn(b.z, b.w);
  *(uint4*)&g_x[i] = *(uint4*)&h[0];
}

// ---------------------------------------------------------------------------
// Prep 2: W [k][n] fp32 -> Wt [which][n][k] fp16; Wq scaled by 1/sqrt(d).
// ---------------------------------------------------------------------------
__global__ __launch_bounds__(256) void prep_w_kernel(
    const float* __restrict__ Wq, const float* __restrict__ Wk,
    const float* __restrict__ Wv) {
  const int which = blockIdx.y;
  const float* __restrict__ W = (which == 0) ? Wq : (which == 1) ? Wk : Wv;
  const float sc = (which == 0) ? 0.08838834764831845f : 1.0f;
  const int idx = blockIdx.x * 256 + threadIdx.x;  // n*1024 + k
  const int n = idx >> 10;
  const int k = idx & 1023;
  g_wt[(size_t)which * DD * EE + idx] = __float2half_rn(W[(size_t)k * DD + n] * sc);
}

// ---------------------------------------------------------------------------
// QKV projection via fp16 HMMA — v4: all-fp16 feed + TWO CTAs per SM
// (__launch_bounds__(256,2): 4 warps/SMSP hide LDG/barrier latency; the
// 384-CTA grid shrinks from 2.6 to 1.3 waves).  KC=32, tile 128x128,
// double-buffered, stride 40.  grid = (128, 3).
// ---------------------------------------------------------------------------
#define KC 32
#define HSTR 40
#define TILE_H (128 * HSTR)

__global__ __launch_bounds__(256, 2) void qkv_hmma_kernel() {
  __shared__ __half Xs[2][TILE_H];
  __shared__ __half Ws[2][TILE_H];

  const int which = blockIdx.y;
  const __half* __restrict__ Wt = g_wt + (size_t)which * DD * EE;
  __half* __restrict__ outp = (which == 0) ? g_q : (which == 1) ? g_k : g_v;

  const int m0 = blockIdx.x * 128;
  const int tid = threadIdx.x;
  const int warp = tid >> 5;
  const int lane = tid & 31;
  const int wm = (warp >> 1) * 32;
  const int wn = (warp & 1) * 64;

  const int ldrow = tid >> 1;        // 0..127
  const int ldk16 = (tid & 1) * 16;  // 0 or 16 (halfs)

  const int a_row = (lane & 7) + 8 * ((lane >> 3) & 1);
  const int a_col = (lane >> 4) * 8;
  const int b_row = (lane & 7) + 8 * (lane >> 4);
  const int b_col = ((lane >> 3) & 1) * 8;

  const uint32_t xs_base = smem_u32(&Xs[0][0]);
  const uint32_t ws_base = smem_u32(&Ws[0][0]);

  const __half* xrow = g_x + (size_t)(m0 + ldrow) * EE;
  const __half* wrow = Wt + (size_t)ldrow * EE;

  float acc[2][8][4];
#pragma unroll
  for (int mt = 0; mt < 2; mt++)
#pragma unroll
    for (int nt = 0; nt < 8; nt++)
#pragma unroll
      for (int i = 0; i < 4; i++) acc[mt][nt][i] = 0.f;

  // ---- stage chunk 0 ----
  {
    uint4 x0 = *(const uint4*)&xrow[ldk16];
    uint4 x1 = *(const uint4*)&xrow[ldk16 + 8];
    uint4 w0 = *(const uint4*)&wrow[ldk16];
    uint4 w1 = *(const uint4*)&wrow[ldk16 + 8];
    *(uint4*)&Xs[0][ldrow * HSTR + ldk16] = x0;
    *(uint4*)&Xs[0][ldrow * HSTR + ldk16 + 8] = x1;
    *(uint4*)&Ws[0][ldrow * HSTR + ldk16] = w0;
    *(uint4*)&Ws[0][ldrow * HSTR + ldk16 + 8] = w1;
  }
  __syncthreads();

  for (int c = 0; c < EE / KC; c++) {
    const int cur = c & 1;
    uint4 x0, x1, w0, w1;
    const bool more = (c + 1 < EE / KC);
    if (more) {
      const int kc = (c + 1) * KC;
      x0 = *(const uint4*)&xrow[kc + ldk16];
      x1 = *(const uint4*)&xrow[kc + ldk16 + 8];
      w0 = *(const uint4*)&wrow[kc + ldk16];
      w1 = *(const uint4*)&wrow[kc + ldk16 + 8];
    }

    const uint32_t xb = xs_base + (uint32_t)(cur * TILE_H * 2);
    const uint32_t wb = ws_base + (uint32_t)(cur * TILE_H * 2);
#pragma unroll
    for (int s = 0; s < 2; s++) {
      uint32_t a[2][4];
#pragma unroll
      for (int mt = 0; mt < 2; mt++) {
        const int row = wm + mt * 16 + a_row;
        ldsm_x4(a[mt], xb + (uint32_t)((row * HSTR + a_col + s * 16) * 2));
      }
      uint32_t bf[8][2];
#pragma unroll
      for (int g = 0; g < 4; g++) {
        uint32_t r[4];
        const int row = wn + g * 16 + b_row;
        ldsm_x4(r, wb + (uint32_t)((row * HSTR + b_col + s * 16) * 2));
        bf[2 * g][0] = r[0]; bf[2 * g][1] = r[1];
        bf[2 * g + 1][0] = r[2]; bf[2 * g + 1][1] = r[3];
      }
#pragma unroll
      for (int mt = 0; mt < 2; mt++)
#pragma unroll
        for (int nt = 0; nt < 8; nt++) mma_f16(acc[mt][nt], a[mt], bf[nt]);
    }

    if (more) {
      const int nxt = cur ^ 1;
      *(uint4*)&Xs[nxt][ldrow * HSTR + ldk16] = x0;
      *(uint4*)&Xs[nxt][ldrow * HSTR + ldk16 + 8] = x1;
      *(uint4*)&Ws[nxt][ldrow * HSTR + ldk16] = w0;
      *(uint4*)&Ws[nxt][ldrow * HSTR + ldk16 + 8] = w1;
    }
    __syncthreads();
  }

  const int fr = lane >> 2;
  const int fc = (lane & 3) * 2;
#pragma unroll
  for (int mt = 0; mt < 2; mt++) {
    const size_t row0 = (size_t)(m0 + wm + mt * 16 + fr);
#pragma unroll
    for (int nt = 0; nt < 8; nt++) {
      const int col = wn + nt * 8 + fc;
      __half2 h01 = __floats2half2_rn(acc[mt][nt][0], acc[mt][nt][1]);
      __half2 h23 = __floats2half2_rn(acc[mt][nt][2], acc[mt][nt][3]);
      *(__half2*)&outp[row0 * DD + col] = h01;
      *(__half2*)&outp[(row0 + 8) * DD + col] = h23;
    }
  }
}

// ---------------------------------------------------------------------------
// Causal flash attention v8 (unchanged — 43.8us): fp16 HMMA, split-K warp
// groups, group-local barriers, end-of-qblk merge.
// ---------------------------------------------------------------------------
#define HST 136
#define QOFF 0
#define MLOFF (320 * HST)
#define ATT_SMEM_B (320 * HST * 2 + 1024)

__global__ __launch_bounds__(256) void attn_hmma_kernel(float* __restrict__ out) {
  extern __shared__ __half smh[];
  const int tid = threadIdx.x;
  const int w = tid >> 5;
  const int g = w >> 2;
  const int wg = w & 3;
  const int lane = tid & 31;
  const int b = blockIdx.y;

  const __half* __restrict__ qp = g_q + (size_t)b * TT * DD;
  const __half* __restrict__ kp = g_k + (size_t)b * TT * DD;
  const __half* __restrict__ vp = g_v + (size_t)b * TT * DD;

  const uint32_t smb = smem_u32(smh);
  const int fr = lane >> 2;
  const int fc = (lane & 3) * 2;
  const int lm = lane >> 3;
  const int r8 = lane & 7;

  const int qa_row = 16 * wg + r8 + 8 * (lm & 1);
  const int qa_colb = 8 * (lm >> 1);
  const int kb_rowoff = 8 * (lm >> 1) + r8;
  const int kb_coloff = 8 * (lm & 1);
  const int vb_rowoff = 8 * (lm & 1) + r8;
  const int vb_coloff = 8 * (lm >> 1);

  const int KOFFg = (64 + 128 * g) * HST;
  const int VOFFg = (128 + 128 * g) * HST;

  const int lt = tid & 127;
  const int ls_r = lt >> 4;
  const int ls_c = lt & 15;
  const int qs_r = tid >> 4;
  const int qs_c = tid & 15;

  float* mlx = (float*)(smh + MLOFF);
  float* Oex = (float*)(smh + 64 * HST);

  for (int pass = 0; pass < 2; pass++) {
    const int qblk = pass ? (31 - (int)blockIdx.x) : (int)blockIdx.x;
    const int nkt = qblk + 1;

#pragma unroll
    for (int it = 0; it < 4; it++) {
      const int r = qs_r + 16 * it;
      uint4 v = *((const uint4*)qp + (size_t)(qblk * 64 + r) * 16 + qs_c);
      *(uint4*)&smh[QOFF + r * HST + qs_c * 8] = v;
    }
    uint4 pk4[8], pv4[8];
#pragma unroll
    for (int it = 0; it < 8; it++) {
      const size_t r = (size_t)g * 64 + ls_r + 8 * it;
      pk4[it] = *((const uint4*)kp + r * 16 + ls_c);
      pv4[it] = *((const uint4*)vp + r * 16 + ls_c);
    }
    __syncthreads();

    uint32_t qa[8][4];
#pragma unroll
    for (int ks = 0; ks < 8; ks++)
      ldsm_x4(qa[ks], smb + (uint32_t)((qa_row * HST + 16 * ks + qa_colb) * 2));

    float m0 = -1e30f, m1 = -1e30f, l0 = 0.f, l1 = 0.f;
    float ov[16][4];
#pragma unroll
    for (int nt = 0; nt < 16; nt++)
#pragma unroll
      for (int i = 0; i < 4; i++) ov[nt][i] = 0.f;

    for (int kt = g; kt < nkt; kt += 2) {
      bar_sync(g + 1, 128);
#pragma unroll
      for (int it = 0; it < 8; it++) {
        const int r = ls_r + 8 * it;
        *(uint4*)&smh[KOFFg + r * HST + ls_c * 8] = pk4[it];
        *(uint4*)&smh[VOFFg + r * HST + ls_c * 8] = pv4[it];
      }
      bar_sync(g + 1, 128);

      if (kt + 2 < nkt) {
        const size_t krow = (size_t)(kt + 2) * 64;
#pragma unroll
        for (int it = 0; it < 8; it++)
          pk4[it] = *((const uint4*)kp + (krow + ls_r + 8 * it) * 16 + ls_c);
      }

      float sc_[8][4];
#pragma unroll
      for (int nt = 0; nt < 8; nt++)
#pragma unroll
        for (int i = 0; i < 4; i++) sc_[nt][i] = 0.f;

#pragma unroll
      for (int ks = 0; ks < 8; ks++) {
        uint32_t bq[4][4];
#pragma unroll
        for (int np = 0; np < 4; np++)
          ldsm_x4(bq[np], smb + (uint32_t)((KOFFg + (16 * np + kb_rowoff) * HST +
                                            16 * ks + kb_coloff) * 2));
#pragma unroll
        for (int nt = 0; nt < 8; nt++)
          mma_f16(sc_[nt], qa[ks], &bq[nt >> 1][(nt & 1) * 2]);
      }

      if (kt + 2 < nkt) {
        const size_t krow = (size_t)(kt + 2) * 64;
#pragma unroll
        for (int it = 0; it < 8; it++)
          pv4[it] = *((const uint4*)vp + (krow + ls_r + 8 * it) * 16 + ls_c);
      }

      if (kt == qblk) {
        const int q0r = qblk * 64 + 16 * wg + fr;
        const int q1r = q0r + 8;
#pragma unroll
        for (int nt = 0; nt < 8; nt++) {
          const int k0 = kt * 64 + nt * 8 + fc;
          if (k0 > q0r) sc_[nt][0] = -1e30f;
          if (k0 + 1 > q0r) sc_[nt][1] = -1e30f;
          if (k0 > q1r) sc_[nt][2] = -1e30f;
          if (k0 + 1 > q1r) sc_[nt][3] = -1e30f;
        }
      }

      float mx0 = sc_[0][0], mx1 = sc_[0][2];
#pragma unroll
      for (int nt = 0; nt < 8; nt++) {
        mx0 = fmaxf(mx0, fmaxf(sc_[nt][0], sc_[nt][1]));
        mx1 = fmaxf(mx1, fmaxf(sc_[nt][2], sc_[nt][3]));
      }
      mx0 = fmaxf(mx0, __shfl_xor_sync(0xffffffffu, mx0, 1));
      mx0 = fmaxf(mx0, __shfl_xor_sync(0xffffffffu, mx0, 2));
      mx1 = fmaxf(mx1, __shfl_xor_sync(0xffffffffu, mx1, 1));
      mx1 = fmaxf(mx1, __shfl_xor_sync(0xffffffffu, mx1, 2));
      const float mn0 = fmaxf(m0, mx0);
      const float mn1 = fmaxf(m1, mx1);
      const float al0 = __expf(m0 - mn0);
      const float al1 = __expf(m1 - mn1);
      m0 = mn0; m1 = mn1;

      uint32_t P2[8][2];
      float s0 = 0.f, s1 = 0.f;
#pragma unroll
      for (int nt = 0; nt < 8; nt++) {
        float p0 = __expf(sc_[nt][0] - mn0);
        float p1 = __expf(sc_[nt][1] - mn0);
        float p2 = __expf(sc_[nt][2] - mn1);
        float p3 = __expf(sc_[nt][3] - mn1);
        s0 += p0 + p1;
        s1 += p2 + p3;
        __half2 h01 = __floats2half2_rn(p0, p1);
        __half2 h23 = __floats2half2_rn(p2, p3);
        P2[nt][0] = *(uint32_t*)&h01;
        P2[nt][1] = *(uint32_t*)&h23;
      }
      s0 += __shfl_xor_sync(0xffffffffu, s0, 1);
      s0 += __shfl_xor_sync(0xffffffffu, s0, 2);
      s1 += __shfl_xor_sync(0xffffffffu, s1, 1);
      s1 += __shfl_xor_sync(0xffffffffu, s1, 2);
      l0 = l0 * al0 + s0;
      l1 = l1 * al1 + s1;

#pragma unroll
      for (int nt = 0; nt < 16; nt++) {
        ov[nt][0] *= al0; ov[nt][1] *= al0;
        ov[nt][2] *= al1; ov[nt][3] *= al1;
      }

#pragma unroll
      for (int kv = 0; kv < 4; kv++) {
        uint32_t av[4] = {P2[2 * kv][0], P2[2 * kv][1],
                          P2[2 * kv + 1][0], P2[2 * kv + 1][1]};
#pragma unroll
        for (int np = 0; np < 8; np++) {
          uint32_t bv[4];
          ldsm_x4_t(bv, smb + (uint32_t)((VOFFg + (16 * kv + vb_rowoff) * HST +
                                          16 * np + vb_coloff) * 2));
          mma_f16(ov[2 * np], av, &bv[0]);
          mma_f16(ov[2 * np + 1], av, &bv[2]);
        }
      }
    }

    // ================= cross-group merge =================
    const int row0 = 16 * wg + fr;
    const int row1 = row0 + 8;
    __syncthreads();
    if ((lane & 3) == 0) {
      mlx[(g * 64 + row0) * 2 + 0] = m0;
      mlx[(g * 64 + row0) * 2 + 1] = l0;
      mlx[(g * 64 + row1) * 2 + 0] = m1;
      mlx[(g * 64 + row1) * 2 + 1] = l1;
    }
    __syncthreads();
    const int og = 1 - g;
    const float mo0 = mlx[(og * 64 + row0) * 2 + 0];
    const float lo0 = mlx[(og * 64 + row0) * 2 + 1];
    const float mo1 = mlx[(og * 64 + row1) * 2 + 0];
    const float lo1 = mlx[(og * 64 + row1) * 2 + 1];
    const float mm0 = fmaxf(m0, mo0);
    const float mm1 = fmaxf(m1, mo1);
    const float sown0 = __expf(m0 - mm0);
    const float sown1 = __expf(m1 - mm1);
    const float lf0 = l0 * sown0 + lo0 * __expf(mo0 - mm0);
    const float lf1 = l1 * sown1 + lo1 * __expf(mo1 - mm1);
#pragma unroll
    for (int nt = 0; nt < 16; nt++) {
      ov[nt][0] *= sown0; ov[nt][1] *= sown0;
      ov[nt][2] *= sown1; ov[nt][3] *= sown1;
    }
    if (g == 1) {
#pragma unroll
      for (int nt = 0; nt < 16; nt++) {
        const int col = nt * 8 + fc;
        *(float2*)&Oex[row0 * 128 + col] = make_float2(ov[nt][0], ov[nt][1]);
        *(float2*)&Oex[row1 * 128 + col] = make_float2(ov[nt][2], ov[nt][3]);
      }
    }
    __syncthreads();
    if (g == 0) {
      const float i0 = 1.f / lf0;
      const float i1 = 1.f / lf1;
      const size_t gr0 = (size_t)b * TT + (size_t)qblk * 64 + row0;
#pragma unroll
      for (int nt = 0; nt < 16; nt++) {
        const int col = nt * 8 + fc;
        float2 p0 = *(const float2*)&Oex[row0 * 128 + col];
        float2 p1 = *(const float2*)&Oex[row1 * 128 + col];
        *(float2*)&out[gr0 * DD + col] =
            make_float2((ov[nt][0] + p0.x) * i0, (ov[nt][1] + p0.y) * i0);
        *(float2*)&out[(gr0 + 8) * DD + col] =
            make_float2((ov[nt][2] + p1.x) * i1, (ov[nt][3] + p1.y) * i1);
      }
    }
  }
}

// ---------------------------------------------------------------------------
extern "C" void kernel_launch(void* const* d_in, const int* in_sizes, int n_in,
                              void* d_out, int out_size) {
  const float* X = (const float*)d_in[0];
  const float* Wq = (const float*)d_in[1];
  const float* Wk = (const float*)d_in[2];
  const float* Wv = (const float*)d_in[3];
  float* out = (float*)d_out;

  prep_x_kernel<<<(MTOT * EE) / (256 * 8), 256>>>(X);
  prep_w_kernel<<<dim3((DD * EE) / 256, 3), 256>>>(Wq, Wk, Wv);
  qkv_hmma_kernel<<<dim3(128, 3), 256>>>();

  cudaFuncSetAttribute((const void*)attn_hmma_kernel,
                       cudaFuncAttributeMaxDynamicSharedMemorySize, ATT_SMEM_B);
  attn_hmma_kernel<<<dim3(16, BATCHN), 256, ATT_SMEM_B>>>(out);
}

// round 16
// speedup vs baseline: 1.3519x; 1.1706x over previous
#include <cuda_runtime.h>
#include <cuda_fp16.h>
#include <cstdint>

#define BATCHN 8
#define TT 2048
#define EE 1024
#define DD 128
#define MTOT (BATCHN*TT)

// fp16 scratch — __device__ globals per allocation rules.
__device__ __align__(16) __half g_x[MTOT*EE];        // 32 MB: X in fp16
__device__ __align__(16) __half g_wt[3*DD*EE];       // 768 KB: W^T fp16 [which][n][k]
__device__ __align__(16) __half g_q[MTOT*DD];
__device__ __align__(16) __half g_k[MTOT*DD];
__device__ __align__(16) __half g_v[MTOT*DD];

__device__ __forceinline__ uint32_t smem_u32(const void* p) {
  uint32_t a;
  asm("{ .reg .u64 t; cvta.to.shared.u64 t, %1; cvt.u32.u64 %0, t; }"
      : "=r"(a) : "l"(p));
  return a;
}
__device__ __forceinline__ void ldsm_x4(uint32_t* r, uint32_t addr) {
  asm volatile(
      "ldmatrix.sync.aligned.m8n8.x4.shared.b16 {%0,%1,%2,%3}, [%4];"
      : "=r"(r[0]), "=r"(r[1]), "=r"(r[2]), "=r"(r[3]) : "r"(addr));
}
__device__ __forceinline__ void ldsm_x4_t(uint32_t* r, uint32_t addr) {
  asm volatile(
      "ldmatrix.sync.aligned.m8n8.x4.trans.shared.b16 {%0,%1,%2,%3}, [%4];"
      : "=r"(r[0]), "=r"(r[1]), "=r"(r[2]), "=r"(r[3]) : "r"(addr));
}
__device__ __forceinline__ void mma_f16(float* c, const uint32_t* a,
                                        const uint32_t* b) {
  asm volatile(
      "mma.sync.aligned.m16n8k16.row.col.f32.f16.f16.f32 "
      "{%0,%1,%2,%3}, {%4,%5,%6,%7}, {%8,%9}, {%0,%1,%2,%3};"
      : "+f"(c[0]), "+f"(c[1]), "+f"(c[2]), "+f"(c[3])
      : "r"(a[0]), "r"(a[1]), "r"(a[2]), "r"(a[3]), "r"(b[0]), "r"(b[1]));
}
__device__ __forceinline__ void bar_sync(int id, int cnt) {
  asm volatile("bar.sync %0, %1;" :: "r"(id), "r"(cnt) : "memory");
}
__device__ __forceinline__ void cp_async16(uint32_t dst, const void* src) {
  asm volatile("cp.async.cg.shared.global [%0], [%1], 16;" :: "r"(dst),
               "l"(src) : "memory");
}
__device__ __forceinline__ void cp_commit() {
  asm volatile("cp.async.commit_group;" ::: "memory");
}
__device__ __forceinline__ void cp_wait1() {
  asm volatile("cp.async.wait_group 1;" ::: "memory");
}

// ---------------------------------------------------------------------------
// Prep 1: X fp32 -> fp16 (memory-bound).  8 floats per thread.
// ---------------------------------------------------------------------------
__global__ __launch_bounds__(256) void prep_x_kernel(const float* __restrict__ X) {
  const size_t i = ((size_t)blockIdx.x * 256 + threadIdx.x) * 8;
  float4 a = *(const float4*)&X[i];
  float4 b = *(const float4*)&X[i + 4];
  __half2 h[4];
  h[0] = __floats2half2_rn(a.x, a.y);
  h[1] = __floats2half2_rn(a.z, a.w);
  h[2] = __floats2half2_rn(b.x, b.y);
  h[3] = __floats2half2_rn(b.z, b.w);
  *(uint4*)&g_x[i] = *(uint4*)&h[0];
}

// ---------------------------------------------------------------------------
// Prep 2: W [k][n] fp32 -> Wt [which][n][k] fp16; Wq scaled by 1/sqrt(d).
// ---------------------------------------------------------------------------
__global__ __launch_bounds__(256) void prep_w_kernel(
    const float* __restrict__ Wq, const float* __restrict__ Wk,
    const float* __restrict__ Wv) {
  const int which = blockIdx.y;
  const float* __restrict__ W = (which == 0) ? Wq : (which == 1) ? Wk : Wv;
  const float sc = (which == 0) ? 0.08838834764831845f : 1.0f;
  const int idx = blockIdx.x * 256 + threadIdx.x;  // n*1024 + k
  const int n = idx >> 10;
  const int k = idx & 1023;
  g_wt[(size_t)which * DD * EE + idx] = __float2half_rn(W[(size_t)k * DD + n] * sc);
}

// ---------------------------------------------------------------------------
// QKV projection via fp16 HMMA — v5: 3-stage cp.async pipeline (wait_group 1
// keeps 2 chunks in flight -> DRAM latency off the critical path; no prefetch
// registers -> 2 CTAs/SM feasible).  KC=32, tile 128x128, stride 40.
// Dynamic smem 60KB/CTA.  grid = (128, 3).
// ---------------------------------------------------------------------------
#define KC 32
#define HSTR 40
#define TILE_H (128 * HSTR)          // 5120 halfs per tile
#define SSTG (2 * TILE_H)            // halfs per stage (X + W)
#define NSTAGE 3
#define GEMM_SMEM_B (NSTAGE * SSTG * 2)   // 61440 bytes

__global__ __launch_bounds__(256, 2) void qkv_hmma_kernel() {
  extern __shared__ __half sg[];

  const int which = blockIdx.y;
  const __half* __restrict__ Wt = g_wt + (size_t)which * DD * EE;
  __half* __restrict__ outp = (which == 0) ? g_q : (which == 1) ? g_k : g_v;

  const int m0 = blockIdx.x * 128;
  const int tid = threadIdx.x;
  const int warp = tid >> 5;
  const int lane = tid & 31;
  const int wm = (warp >> 1) * 32;
  const int wn = (warp & 1) * 64;

  const int ldrow = tid >> 1;        // 0..127
  const int ldk16 = (tid & 1) * 16;  // 0 or 16 (halfs)

  const int a_row = (lane & 7) + 8 * ((lane >> 3) & 1);
  const int a_col = (lane >> 4) * 8;
  const int b_row = (lane & 7) + 8 * (lane >> 4);
  const int b_col = ((lane >> 3) & 1) * 8;

  const uint32_t base = smem_u32(sg);
  const __half* xrow = g_x + (size_t)(m0 + ldrow) * EE;
  const __half* wrow = Wt + (size_t)ldrow * EE;
  const uint32_t dst_off = (uint32_t)((ldrow * HSTR + ldk16) * 2);

  float acc[2][8][4];
#pragma unroll
  for (int mt = 0; mt < 2; mt++)
#pragma unroll
    for (int nt = 0; nt < 8; nt++)
#pragma unroll
      for (int i = 0; i < 4; i++) acc[mt][nt][i] = 0.f;

  // ---- prologue: issue chunks 0..NSTAGE-2 ----
#pragma unroll
  for (int s = 0; s < NSTAGE - 1; s++) {
    const int kc = s * KC;
    const uint32_t xs = base + (uint32_t)(s * SSTG * 2);
    cp_async16(xs + dst_off, xrow + kc + ldk16);
    cp_async16(xs + dst_off + 16, xrow + kc + ldk16 + 8);
    cp_async16(xs + (uint32_t)(TILE_H * 2) + dst_off, wrow + kc + ldk16);
    cp_async16(xs + (uint32_t)(TILE_H * 2) + dst_off + 16, wrow + kc + ldk16 + 8);
    cp_commit();
  }

  for (int c = 0; c < EE / KC; c++) {
    cp_wait1();        // oldest group (chunk c) complete
    __syncthreads();   // visible to all threads; stage (c+2)%3 free

    // issue chunk c+2 into stage (c+2)%NSTAGE
    if (c + NSTAGE - 1 < EE / KC) {
      const int cn = c + NSTAGE - 1;
      const int kc = cn * KC;
      const uint32_t xs = base + (uint32_t)((cn % NSTAGE) * SSTG * 2);
      cp_async16(xs + dst_off, xrow + kc + ldk16);
      cp_async16(xs + dst_off + 16, xrow + kc + ldk16 + 8);
      cp_async16(xs + (uint32_t)(TILE_H * 2) + dst_off, wrow + kc + ldk16);
      cp_async16(xs + (uint32_t)(TILE_H * 2) + dst_off + 16, wrow + kc + ldk16 + 8);
    }
    cp_commit();

    // ---- compute chunk c from stage c%NSTAGE ----
    const uint32_t xb = base + (uint32_t)((c % NSTAGE) * SSTG * 2);
    const uint32_t wb = xb + (uint32_t)(TILE_H * 2);
#pragma unroll
    for (int s = 0; s < 2; s++) {
      uint32_t a[2][4];
#pragma unroll
      for (int mt = 0; mt < 2; mt++) {
        const int row = wm + mt * 16 + a_row;
        ldsm_x4(a[mt], xb + (uint32_t)((row * HSTR + a_col + s * 16) * 2));
      }
      uint32_t bf[8][2];
#pragma unroll
      for (int g = 0; g < 4; g++) {
        uint32_t r[4];
        const int row = wn + g * 16 + b_row;
        ldsm_x4(r, wb + (uint32_t)((row * HSTR + b_col + s * 16) * 2));
        bf[2 * g][0] = r[0]; bf[2 * g][1] = r[1];
        bf[2 * g + 1][0] = r[2]; bf[2 * g + 1][1] = r[3];
      }
#pragma unroll
      for (int mt = 0; mt < 2; mt++)
#pragma unroll
        for (int nt = 0; nt < 8; nt++) mma_f16(acc[mt][nt], a[mt], bf[nt]);
    }
  }

  const int fr = lane >> 2;
  const int fc = (lane & 3) * 2;
#pragma unroll
  for (int mt = 0; mt < 2; mt++) {
    const size_t row0 = (size_t)(m0 + wm + mt * 16 + fr);
#pragma unroll
    for (int nt = 0; nt < 8; nt++) {
      const int col = wn + nt * 8 + fc;
      __half2 h01 = __floats2half2_rn(acc[mt][nt][0], acc[mt][nt][1]);
      __half2 h23 = __floats2half2_rn(acc[mt][nt][2], acc[mt][nt][3]);
      *(__half2*)&outp[row0 * DD + col] = h01;
      *(__half2*)&outp[(row0 + 8) * DD + col] = h23;
    }
  }
}

// ---------------------------------------------------------------------------
// Causal flash attention v8 (unchanged — 44us): fp16 HMMA, split-K warp
// groups, group-local barriers, end-of-qblk merge.
// ---------------------------------------------------------------------------
#define HST 136
#define QOFF 0
#define MLOFF (320 * HST)
#define ATT_SMEM_B (320 * HST * 2 + 1024)

__global__ __launch_bounds__(256) void attn_hmma_kernel(float* __restrict__ out) {
  extern __shared__ __half smh[];
  const int tid = threadIdx.x;
  const int w = tid >> 5;
  const int g = w >> 2;
  const int wg = w & 3;
  const int lane = tid & 31;
  const int b = blockIdx.y;

  const __half* __restrict__ qp = g_q + (size_t)b * TT * DD;
  const __half* __restrict__ kp = g_k + (size_t)b * TT * DD;
  const __half* __restrict__ vp = g_v + (size_t)b * TT * DD;

  const uint32_t smb = smem_u32(smh);
  const int fr = lane >> 2;
  const int fc = (lane & 3) * 2;
  const int lm = lane >> 3;
  const int r8 = lane & 7;

  const int qa_row = 16 * wg + r8 + 8 * (lm & 1);
  const int qa_colb = 8 * (lm >> 1);
  const int kb_rowoff = 8 * (lm >> 1) + r8;
  const int kb_coloff = 8 * (lm & 1);
  const int vb_rowoff = 8 * (lm & 1) + r8;
  const int vb_coloff = 8 * (lm >> 1);

  const int KOFFg = (64 + 128 * g) * HST;
  const int VOFFg = (128 + 128 * g) * HST;

  const int lt = tid & 127;
  const int ls_r = lt >> 4;
  const int ls_c = lt & 15;
  const int qs_r = tid >> 4;
  const int qs_c = tid & 15;

  float* mlx = (float*)(smh + MLOFF);
  float* Oex = (float*)(smh + 64 * HST);

  for (int pass = 0; pass < 2; pass++) {
    const int qblk = pass ? (31 - (int)blockIdx.x) : (int)blockIdx.x;
    const int nkt = qblk + 1;

#pragma unroll
    for (int it = 0; it < 4; it++) {
      const int r = qs_r + 16 * it;
      uint4 v = *((const uint4*)qp + (size_t)(qblk * 64 + r) * 16 + qs_c);
      *(uint4*)&smh[QOFF + r * HST + qs_c * 8] = v;
    }
    uint4 pk4[8], pv4[8];
#pragma unroll
    for (int it = 0; it < 8; it++) {
      const size_t r = (size_t)g * 64 + ls_r + 8 * it;
      pk4[it] = *((const uint4*)kp + r * 16 + ls_c);
      pv4[it] = *((const uint4*)vp + r * 16 + ls_c);
    }
    __syncthreads();

    uint32_t qa[8][4];
#pragma unroll
    for (int ks = 0; ks < 8; ks++)
      ldsm_x4(qa[ks], smb + (uint32_t)((qa_row * HST + 16 * ks + qa_colb) * 2));

    float m0 = -1e30f, m1 = -1e30f, l0 = 0.f, l1 = 0.f;
    float ov[16][4];
#pragma unroll
    for (int nt = 0; nt < 16; nt++)
#pragma unroll
      for (int i = 0; i < 4; i++) ov[nt][i] = 0.f;

    for (int kt = g; kt < nkt; kt += 2) {
      bar_sync(g + 1, 128);
#pragma unroll
      for (int it = 0; it < 8; it++) {
        const int r = ls_r + 8 * it;
        *(uint4*)&smh[KOFFg + r * HST + ls_c * 8] = pk4[it];
        *(uint4*)&smh[VOFFg + r * HST + ls_c * 8] = pv4[it];
      }
      bar_sync(g + 1, 128);

      if (kt + 2 < nkt) {
        const size_t krow = (size_t)(kt + 2) * 64;
#pragma unroll
        for (int it = 0; it < 8; it++)
          pk4[it] = *((const uint4*)kp + (krow + ls_r + 8 * it) * 16 + ls_c);
      }

      float sc_[8][4];
#pragma unroll
      for (int nt = 0; nt < 8; nt++)
#pragma unroll
        for (int i = 0; i < 4; i++) sc_[nt][i] = 0.f;

#pragma unroll
      for (int ks = 0; ks < 8; ks++) {
        uint32_t bq[4][4];
#pragma unroll
        for (int np = 0; np < 4; np++)
          ldsm_x4(bq[np], smb + (uint32_t)((KOFFg + (16 * np + kb_rowoff) * HST +
                                            16 * ks + kb_coloff) * 2));
#pragma unroll
        for (int nt = 0; nt < 8; nt++)
          mma_f16(sc_[nt], qa[ks], &bq[nt >> 1][(nt & 1) * 2]);
      }

      if (kt + 2 < nkt) {
        const size_t krow = (size_t)(kt + 2) * 64;
#pragma unroll
        for (int it = 0; it < 8; it++)
          pv4[it] = *((const uint4*)vp + (krow + ls_r + 8 * it) * 16 + ls_c);
      }

      if (kt == qblk) {
        const int q0r = qblk * 64 + 16 * wg + fr;
        const int q1r = q0r + 8;
#pragma unroll
        for (int nt = 0; nt < 8; nt++) {
          const int k0 = kt * 64 + nt * 8 + fc;
          if (k0 > q0r) sc_[nt][0] = -1e30f;
          if (k0 + 1 > q0r) sc_[nt][1] = -1e30f;
          if (k0 > q1r) sc_[nt][2] = -1e30f;
          if (k0 + 1 > q1r) sc_[nt][3] = -1e30f;
        }
      }

      float mx0 = sc_[0][0], mx1 = sc_[0][2];
#pragma unroll
      for (int nt = 0; nt < 8; nt++) {
        mx0 = fmaxf(mx0, fmaxf(sc_[nt][0], sc_[nt][1]));
        mx1 = fmaxf(mx1, fmaxf(sc_[nt][2], sc_[nt][3]));
      }
      mx0 = fmaxf(mx0, __shfl_xor_sync(0xffffffffu, mx0, 1));
      mx0 = fmaxf(mx0, __shfl_xor_sync(0xffffffffu, mx0, 2));
      mx1 = fmaxf(mx1, __shfl_xor_sync(0xffffffffu, mx1, 1));
      mx1 = fmaxf(mx1, __shfl_xor_sync(0xffffffffu, mx1, 2));
      const float mn0 = fmaxf(m0, mx0);
      const float mn1 = fmaxf(m1, mx1);
      const float al0 = __expf(m0 - mn0);
      const float al1 = __expf(m1 - mn1);
      m0 = mn0; m1 = mn1;

      uint32_t P2[8][2];
      float s0 = 0.f, s1 = 0.f;
#pragma unroll
      for (int nt = 0; nt < 8; nt++) {
        float p0 = __expf(sc_[nt][0] - mn0);
        float p1 = __expf(sc_[nt][1] - mn0);
        float p2 = __expf(sc_[nt][2] - mn1);
        float p3 = __expf(sc_[nt][3] - mn1);
        s0 += p0 + p1;
        s1 += p2 + p3;
        __half2 h01 = __floats2half2_rn(p0, p1);
        __half2 h23 = __floats2half2_rn(p2, p3);
        P2[nt][0] = *(uint32_t*)&h01;
        P2[nt][1] = *(uint32_t*)&h23;
      }
      s0 += __shfl_xor_sync(0xffffffffu, s0, 1);
      s0 += __shfl_xor_sync(0xffffffffu, s0, 2);
      s1 += __shfl_xor_sync(0xffffffffu, s1, 1);
      s1 += __shfl_xor_sync(0xffffffffu, s1, 2);
      l0 = l0 * al0 + s0;
      l1 = l1 * al1 + s1;

#pragma unroll
      for (int nt = 0; nt < 16; nt++) {
        ov[nt][0] *= al0; ov[nt][1] *= al0;
        ov[nt][2] *= al1; ov[nt][3] *= al1;
      }

#pragma unroll
      for (int kv = 0; kv < 4; kv++) {
        uint32_t av[4] = {P2[2 * kv][0], P2[2 * kv][1],
                          P2[2 * kv + 1][0], P2[2 * kv + 1][1]};
#pragma unroll
        for (int np = 0; np < 8; np++) {
          uint32_t bv[4];
          ldsm_x4_t(bv, smb + (uint32_t)((VOFFg + (16 * kv + vb_rowoff) * HST +
                                          16 * np + vb_coloff) * 2));
          mma_f16(ov[2 * np], av, &bv[0]);
          mma_f16(ov[2 * np + 1], av, &bv[2]);
        }
      }
    }

    // ================= cross-group merge =================
    const int row0 = 16 * wg + fr;
    const int row1 = row0 + 8;
    __syncthreads();
    if ((lane & 3) == 0) {
      mlx[(g * 64 + row0) * 2 + 0] = m0;
      mlx[(g * 64 + row0) * 2 + 1] = l0;
      mlx[(g * 64 + row1) * 2 + 0] = m1;
      mlx[(g * 64 + row1) * 2 + 1] = l1;
    }
    __syncthreads();
    const int og = 1 - g;
    const float mo0 = mlx[(og * 64 + row0) * 2 + 0];
    const float lo0 = mlx[(og * 64 + row0) * 2 + 1];
    const float mo1 = mlx[(og * 64 + row1) * 2 + 0];
    const float lo1 = mlx[(og * 64 + row1) * 2 + 1];
    const float mm0 = fmaxf(m0, mo0);
    const float mm1 = fmaxf(m1, mo1);
    const float sown0 = __expf(m0 - mm0);
    const float sown1 = __expf(m1 - mm1);
    const float lf0 = l0 * sown0 + lo0 * __expf(mo0 - mm0);
    const float lf1 = l1 * sown1 + lo1 * __expf(mo1 - mm1);
#pragma unroll
    for (int nt = 0; nt < 16; nt++) {
      ov[nt][0] *= sown0; ov[nt][1] *= sown0;
      ov[nt][2] *= sown1; ov[nt][3] *= sown1;
    }
    if (g == 1) {
#pragma unroll
      for (int nt = 0; nt < 16; nt++) {
        const int col = nt * 8 + fc;
        *(float2*)&Oex[row0 * 128 + col] = make_float2(ov[nt][0], ov[nt][1]);
        *(float2*)&Oex[row1 * 128 + col] = make_float2(ov[nt][2], ov[nt][3]);
      }
    }
    __syncthreads();
    if (g == 0) {
      const float i0 = 1.f / lf0;
      const float i1 = 1.f / lf1;
      const size_t gr0 = (size_t)b * TT + (size_t)qblk * 64 + row0;
#pragma unroll
      for (int nt = 0; nt < 16; nt++) {
        const int col = nt * 8 + fc;
        float2 p0 = *(const float2*)&Oex[row0 * 128 + col];
        float2 p1 = *(const float2*)&Oex[row1 * 128 + col];
        *(float2*)&out[gr0 * DD + col] =
            make_float2((ov[nt][0] + p0.x) * i0, (ov[nt][1] + p0.y) * i0);
        *(float2*)&out[(gr0 + 8) * DD + col] =
            make_float2((ov[nt][2] + p1.x) * i1, (ov[nt][3] + p1.y) * i1);
      }
    }
  }
}

// ---------------------------------------------------------------------------
extern "C" void kernel_launch(void* const* d_in, const int* in_sizes, int n_in,
                              void* d_out, int out_size) {
  const float* X = (const float*)d_in[0];
  const float* Wq = (const float*)d_in[1];
  const float* Wk = (const float*)d_in[2];
  const float* Wv = (const float*)d_in[3];
  float* out = (float*)d_out;

  prep_x_kernel<<<(MTOT * EE) / (256 * 8), 256>>>(X);
  prep_w_kernel<<<dim3((DD * EE) / 256, 3), 256>>>(Wq, Wk, Wv);

  cudaFuncSetAttribute((const void*)qkv_hmma_kernel,
                       cudaFuncAttributeMaxDynamicSharedMemorySize, GEMM_SMEM_B);
  qkv_hmma_kernel<<<dim3(128, 3), 256, GEMM_SMEM_B>>>();

  cudaFuncSetAttribute((const void*)attn_hmma_kernel,
                       cudaFuncAttributeMaxDynamicSharedMemorySize, ATT_SMEM_B);
  attn_hmma_kernel<<<dim3(16, BATCHN), 256, ATT_SMEM_B>>>(out);
}